// round 15
// baseline (speedup 1.0000x reference)
#include <cuda_runtime.h>
#include <cuda_bf16.h>

#define SEQ 4096
#define DIM 768
#define NH  12
#define HD  64

typedef __nv_bfloat16  bf16;
typedef __nv_bfloat162 bf162;

// ---------------- scratch (static device arrays; no allocation) ----------------
__device__ bf16 g_xh [SEQ * DIM],      g_xl [SEQ * DIM];
__device__ bf16 g_wqh[3 * DIM * DIM],  g_wql[3 * DIM * DIM];
__device__ bf16 g_woh[DIM * DIM],      g_wol[DIM * DIM];
__device__ bf16 g_qkvh[2 * NH * SEQ * HD], g_qkvl[2 * NH * SEQ * HD]; // Q,K head-major
__device__ bf16 g_vth[NH * HD * SEQ],  g_vtl[NH * HD * SEQ];          // V transposed [h][d][key]
__device__ bf16 g_ah [SEQ * DIM],      g_al [SEQ * DIM];

// ---------------- helpers ----------------
__device__ __forceinline__ void mma_bf16(float d[4], const unsigned a[4],
                                         unsigned b0, unsigned b1) {
    asm volatile(
        "mma.sync.aligned.m16n8k16.row.col.f32.bf16.bf16.f32 "
        "{%0,%1,%2,%3}, {%4,%5,%6,%7}, {%8,%9}, {%0,%1,%2,%3};\n"
        : "+f"(d[0]), "+f"(d[1]), "+f"(d[2]), "+f"(d[3])
        : "r"(a[0]), "r"(a[1]), "r"(a[2]), "r"(a[3]), "r"(b0), "r"(b1));
}

__device__ __forceinline__ void ldsm4(unsigned& r0, unsigned& r1,
                                      unsigned& r2, unsigned& r3, unsigned a) {
    asm volatile("ldmatrix.sync.aligned.m8n8.x4.shared.b16 {%0,%1,%2,%3}, [%4];"
                 : "=r"(r0), "=r"(r1), "=r"(r2), "=r"(r3) : "r"(a));
}

__device__ __forceinline__ unsigned su32(const void* p) {
    return (unsigned)__cvta_generic_to_shared(p);
}

__device__ __forceinline__ void cpa16(void* s, const void* g) {
    unsigned sa = (unsigned)__cvta_generic_to_shared(s);
    asm volatile("cp.async.cg.shared.global [%0], [%1], 16;" :: "r"(sa), "l"(g));
}
__device__ __forceinline__ void cpa_commit() { asm volatile("cp.async.commit_group;"); }
template <int Npend>
__device__ __forceinline__ void cpa_wait() { asm volatile("cp.async.wait_group %0;" :: "n"(Npend)); }

__device__ __forceinline__ unsigned packf(float a, float b) {
    bf162 t = __floats2bfloat162_rn(a, b);
    return *reinterpret_cast<unsigned*>(&t);
}
__device__ __forceinline__ float lo_f(unsigned u) { return __uint_as_float(u << 16); }
__device__ __forceinline__ float hi_f(unsigned u) { return __uint_as_float(u & 0xffff0000u); }

// 2^x on the MUFU pipe (offloads the fma pipe; err ~2^-22)
__device__ __forceinline__ float fexp2(float x) {
    float y; asm("ex2.approx.f32 %0, %1;" : "=f"(y) : "f"(x)); return y;
}
#define L2E 1.4426950408889634f

// ---------------- fp32 -> bf16 hi/lo split ----------------
__global__ void split_kernel(const float* __restrict__ src,
                             bf16* __restrict__ h, bf16* __restrict__ l, int n) {
    int i = blockIdx.x * 256 + threadIdx.x;
    if (i < n) {
        float v  = src[i];
        bf16 hi = __float2bfloat16_rn(v);
        h[i] = hi;
        l[i] = __float2bfloat16_rn(v - __bfloat162float(hi));
    }
}

// ---------------- GEMM (NT), split-bf16 x3, cp.async double-buffered ----------------
// NOW __launch_bounds__(256, 2): smem 81920x2=163840<227K, regs 128 -> 2 CTAs/SM
// (4 warps/SMSP) so one CTA's mma covers the other's load/sync gaps.
template <int MODE, int N, int K>
__global__ void __launch_bounds__(256, 2)
gemm_bf16x3(const bf16* __restrict__ Agh, const bf16* __restrict__ Agl,
            const bf16* __restrict__ Bgh, const bf16* __restrict__ Bgl,
            const float* __restrict__ bias, float* __restrict__ C)
{
    extern __shared__ bf16 smg[];
    const int TS = 128 * 40;

    const int tid = threadIdx.x, lane = tid & 31, warp = tid >> 5;
    const int wm = warp >> 1, wn = warp & 1;
    const int m0 = blockIdx.y * 128, n0 = blockIdx.x * 128;

    float acc[2][8][4];
#pragma unroll
    for (int mt = 0; mt < 2; mt++)
#pragma unroll
        for (int nt = 0; nt < 8; nt++)
#pragma unroll
            for (int e = 0; e < 4; e++) acc[mt][nt][e] = 0.f;

    const int lrow  = tid >> 2;
    const int lcol8 = (tid & 3) * 8;

#define GEMM_ISSUE(K0, S)                                                          \
    {                                                                              \
        bf16* b = smg + (S) * 4 * TS;                                              \
        _Pragma("unroll")                                                          \
        for (int i_ = 0; i_ < 2; i_++) {                                           \
            int row = lrow + 64 * i_;                                              \
            cpa16(b + row * 40 + lcol8,                                            \
                  Agh + (size_t)(m0 + row) * K + (K0) + lcol8);                    \
            cpa16(b + TS + row * 40 + lcol8,                                       \
                  Agl + (size_t)(m0 + row) * K + (K0) + lcol8);                    \
            cpa16(b + 2 * TS + row * 40 + lcol8,                                   \
                  Bgh + (size_t)(n0 + row) * K + (K0) + lcol8);                    \
            cpa16(b + 3 * TS + row * 40 + lcol8,                                   \
                  Bgl + (size_t)(n0 + row) * K + (K0) + lcol8);                    \
        }                                                                          \
        cpa_commit();                                                              \
    }

    GEMM_ISSUE(0, 0);

    const int KT = K / 32;
    for (int kt = 0; kt < KT; kt++) {
        if (kt + 1 < KT) { GEMM_ISSUE((kt + 1) * 32, (kt + 1) & 1); cpa_wait<1>(); }
        else             { cpa_wait<0>(); }
        __syncthreads();

        const bf16* As_h = smg + (kt & 1) * 4 * TS;
        const bf16* As_l = As_h + TS;
        const bf16* Bs_h = As_h + 2 * TS;
        const bf16* Bs_l = As_h + 3 * TS;

#pragma unroll
        for (int kk = 0; kk < 2; kk++) {
            const int c0 = kk * 16 + (lane & 3) * 2;
            unsigned ah[2][4], al_[2][4], bh[8][2], bl_[8][2];
#pragma unroll
            for (int mt = 0; mt < 2; mt++) {
                int r = wm * 32 + mt * 16 + (lane >> 2);
                ah[mt][0]  = *(const unsigned*)&As_h[r * 40 + c0];
                ah[mt][1]  = *(const unsigned*)&As_h[(r + 8) * 40 + c0];
                ah[mt][2]  = *(const unsigned*)&As_h[r * 40 + c0 + 8];
                ah[mt][3]  = *(const unsigned*)&As_h[(r + 8) * 40 + c0 + 8];
                al_[mt][0] = *(const unsigned*)&As_l[r * 40 + c0];
                al_[mt][1] = *(const unsigned*)&As_l[(r + 8) * 40 + c0];
                al_[mt][2] = *(const unsigned*)&As_l[r * 40 + c0 + 8];
                al_[mt][3] = *(const unsigned*)&As_l[(r + 8) * 40 + c0 + 8];
            }
#pragma unroll
            for (int nt = 0; nt < 8; nt++) {
                int n = wn * 64 + nt * 8 + (lane >> 2);
                bh[nt][0]  = *(const unsigned*)&Bs_h[n * 40 + c0];
                bh[nt][1]  = *(const unsigned*)&Bs_h[n * 40 + c0 + 8];
                bl_[nt][0] = *(const unsigned*)&Bs_l[n * 40 + c0];
                bl_[nt][1] = *(const unsigned*)&Bs_l[n * 40 + c0 + 8];
            }
#pragma unroll
            for (int mt = 0; mt < 2; mt++)
#pragma unroll
                for (int nt = 0; nt < 8; nt++) {
                    mma_bf16(acc[mt][nt], ah[mt],  bh[nt][0],  bh[nt][1]);
                    mma_bf16(acc[mt][nt], ah[mt],  bl_[nt][0], bl_[nt][1]);
                    mma_bf16(acc[mt][nt], al_[mt], bh[nt][0],  bh[nt][1]);
                }
        }
        __syncthreads();
    }

    // epilogue
#pragma unroll
    for (int mt = 0; mt < 2; mt++) {
        const int m = m0 + wm * 32 + mt * 16 + (lane >> 2);
#pragma unroll
        for (int nt = 0; nt < 8; nt++) {
            const int n = n0 + wn * 64 + nt * 8 + (lane & 3) * 2;
            const float b0 = bias[n], b1 = bias[n + 1];
            float v[4];
            v[0] = acc[mt][nt][0] + b0; v[1] = acc[mt][nt][1] + b1;
            v[2] = acc[mt][nt][2] + b0; v[3] = acc[mt][nt][3] + b1;
            if (MODE == 0) {
                C[(size_t)m * N + n]           = v[0];
                C[(size_t)m * N + n + 1]       = v[1];
                C[(size_t)(m + 8) * N + n]     = v[2];
                C[(size_t)(m + 8) * N + n + 1] = v[3];
            } else {
#pragma unroll
                for (int e = 0; e < 4; e++) {
                    const int mm = m + ((e >> 1) & 1) * 8;
                    const int nn = n + (e & 1);
                    const int which = nn / DIM;
                    const int rem   = nn - which * DIM;   // h*64+d
                    bf16 hi = __float2bfloat16_rn(v[e]);
                    bf16 lo = __float2bfloat16_rn(v[e] - __bfloat162float(hi));
                    if (which == 2) {                     // V: transposed [h*64+d][key]
                        const size_t idx = (size_t)rem * SEQ + mm;
                        g_vth[idx] = hi; g_vtl[idx] = lo;
                    } else {                              // Q,K: [which][h][n][d]
                        const size_t idx =
                            (((size_t)which * NH + (rem >> 6)) * SEQ + mm) * HD + (rem & 63);
                        g_qkvh[idx] = hi; g_qkvl[idx] = lo;
                    }
                }
            }
        }
    }
#undef GEMM_ISSUE
}

// ---------------- Flash attention: 128q/256t, Q staged in K/V stage-0 buffers ----------------
// (proven 755us version: 73728B smem + 128-reg cap -> 2 CTAs/SM)
__global__ void __launch_bounds__(256, 2)
flash_mma()
{
    extern __shared__ char smraw[];
    bf16* Kbuf = (bf16*)smraw;              // [2 stages][Kh|Kl][64*72]
    bf16* Vbuf = Kbuf + 2 * 2 * 64 * 72;    // [2 stages][Vth|Vtl][64*72]  (d, key)
    const int KTS = 64 * 72;
    bf16* Qh = Kbuf;                        // Q staged in stage0 of Kbuf
    bf16* Ql = Vbuf;                        // Q-low staged in stage0 of Vbuf

    const int h  = blockIdx.y;
    const int q0 = blockIdx.x * 128;
    const int tid = threadIdx.x, lane = tid & 31, w = tid >> 5;

    const bf16* Qg_h = g_qkvh + ((size_t)(0 * NH + h) * SEQ + q0) * HD;
    const bf16* Qg_l = g_qkvl + ((size_t)(0 * NH + h) * SEQ + q0) * HD;
    const bf16* Kg_h = g_qkvh + (size_t)(NH + h) * SEQ * HD;
    const bf16* Kg_l = g_qkvl + (size_t)(NH + h) * SEQ * HD;
    const bf16* Vg_h = g_vth + (size_t)h * HD * SEQ;   // [d][key]
    const bf16* Vg_l = g_vtl + (size_t)h * HD * SEQ;

    const int lt = lane >> 3, lrr = lane & 7;
    const unsigned lm_off = (((lt >> 1) * 8 + lrr) * 72 + (lt & 1) * 8) * 2;

    const int frow  = tid >> 3;        // 0..31
    const int fcol8 = (tid & 7) * 8;   // 0..56

#define FLASH_ISSUE(KT_, S)                                                        \
    {                                                                              \
        bf16* kb = Kbuf + (S) * 2 * KTS;                                           \
        bf16* vb = Vbuf + (S) * 2 * KTS;                                           \
        _Pragma("unroll")                                                          \
        for (int i_ = 0; i_ < 2; i_++) {                                           \
            int row = frow + 32 * i_;                                              \
            cpa16(kb + row * 72 + fcol8,                                           \
                  Kg_h + (size_t)((KT_) * 64 + row) * 64 + fcol8);                 \
            cpa16(kb + KTS + row * 72 + fcol8,                                     \
                  Kg_l + (size_t)((KT_) * 64 + row) * 64 + fcol8);                 \
            cpa16(vb + row * 72 + fcol8,                                           \
                  Vg_h + (size_t)row * SEQ + (KT_) * 64 + fcol8);                  \
            cpa16(vb + KTS + row * 72 + fcol8,                                     \
                  Vg_l + (size_t)row * SEQ + (KT_) * 64 + fcol8);                  \
        }                                                                          \
        cpa_commit();                                                              \
    }

    // --- stage Q in the (not yet used) stage-0 K/V buffers, pre-scaled by 1/8 ---
    const bf162 sc = __floats2bfloat162_rn(0.125f, 0.125f);
#pragma unroll
    for (int i = 0; i < 4; i++) {
        int c = tid + 256 * i;
        int row = c >> 3, col8 = (c & 7) * 8;
        uint4 vh = *(const uint4*)&Qg_h[row * 64 + col8];
        uint4 vl = *(const uint4*)&Qg_l[row * 64 + col8];
        bf162* ph = (bf162*)&vh;
        bf162* pl = (bf162*)&vl;
#pragma unroll
        for (int e = 0; e < 4; e++) { ph[e] = __hmul2(ph[e], sc); pl[e] = __hmul2(pl[e], sc); }
        *(uint4*)&Qh[row * 72 + col8] = vh;
        *(uint4*)&Ql[row * 72 + col8] = vl;
    }
    __syncthreads();

    // Q fragments -> registers (persist across all key tiles)
    unsigned qfh[4][4], qfl[4][4];
    {
        const int r = w * 16 + (lane >> 2);
#pragma unroll
        for (int kk = 0; kk < 4; kk++) {
            const int c0 = kk * 16 + (lane & 3) * 2;
            qfh[kk][0] = *(unsigned*)&Qh[r * 72 + c0];
            qfh[kk][1] = *(unsigned*)&Qh[(r + 8) * 72 + c0];
            qfh[kk][2] = *(unsigned*)&Qh[r * 72 + c0 + 8];
            qfh[kk][3] = *(unsigned*)&Qh[(r + 8) * 72 + c0 + 8];
            qfl[kk][0] = *(unsigned*)&Ql[r * 72 + c0];
            qfl[kk][1] = *(unsigned*)&Ql[(r + 8) * 72 + c0];
            qfl[kk][2] = *(unsigned*)&Ql[r * 72 + c0 + 8];
            qfl[kk][3] = *(unsigned*)&Ql[(r + 8) * 72 + c0 + 8];
        }
    }
    __syncthreads();   // all Q reads done before the pipeline overwrites stage 0

    FLASH_ISSUE(0, 0);

    float o[8][4];
#pragma unroll
    for (int nt = 0; nt < 8; nt++)
#pragma unroll
        for (int e = 0; e < 4; e++) o[nt][e] = 0.f;
    float m0r = -1e30f, m1r = -1e30f, l0 = 0.f, l1 = 0.f;

    const int NKT = SEQ / 64;
    for (int kt = 0; kt < NKT; kt++) {
        if (kt + 1 < NKT) { FLASH_ISSUE(kt + 1, (kt + 1) & 1); cpa_wait<1>(); }
        else              { cpa_wait<0>(); }
        __syncthreads();

        const bf16* Kh = Kbuf + (kt & 1) * 2 * KTS;
        const bf16* Kl = Kh + KTS;
        const bf16* Vh = Vbuf + (kt & 1) * 2 * KTS;
        const bf16* Vl = Vh + KTS;
        const unsigned khA = su32(Kh) + lm_off;
        const unsigned klA = su32(Kl) + lm_off;
        const unsigned vhA = su32(Vh) + lm_off;
        const unsigned vlA = su32(Vl) + lm_off;

        // S = (Q/8) K^T — fragments via ldmatrix.x4
        float s[8][4];
#pragma unroll
        for (int nt = 0; nt < 8; nt++)
#pragma unroll
            for (int e = 0; e < 4; e++) s[nt][e] = 0.f;
#pragma unroll
        for (int kk = 0; kk < 4; kk++) {
            const unsigned cof = kk * 16 * 2;
            unsigned bh[8][2], bl_[8][2];
#pragma unroll
            for (int g = 0; g < 4; g++) {
                ldsm4(bh[2 * g][0], bh[2 * g][1], bh[2 * g + 1][0], bh[2 * g + 1][1],
                      khA + g * (16 * 72 * 2) + cof);
                ldsm4(bl_[2 * g][0], bl_[2 * g][1], bl_[2 * g + 1][0], bl_[2 * g + 1][1],
                      klA + g * (16 * 72 * 2) + cof);
            }
#pragma unroll
            for (int nt = 0; nt < 8; nt++) {
                mma_bf16(s[nt], qfh[kk], bh[nt][0], bh[nt][1]);
                mma_bf16(s[nt], qfl[kk], bh[nt][0], bh[nt][1]);
                mma_bf16(s[nt], qfh[kk], bl_[nt][0], bl_[nt][1]);
            }
        }

        // online softmax via MUFU ex2 (rows r=lane/4 and r+8); reduce across lane%4
        float tm0 = -1e30f, tm1 = -1e30f;
#pragma unroll
        for (int nt = 0; nt < 8; nt++) {
            tm0 = fmaxf(tm0, fmaxf(s[nt][0], s[nt][1]));
            tm1 = fmaxf(tm1, fmaxf(s[nt][2], s[nt][3]));
        }
        tm0 = fmaxf(tm0, __shfl_xor_sync(0xffffffffu, tm0, 1));
        tm0 = fmaxf(tm0, __shfl_xor_sync(0xffffffffu, tm0, 2));
        tm1 = fmaxf(tm1, __shfl_xor_sync(0xffffffffu, tm1, 1));
        tm1 = fmaxf(tm1, __shfl_xor_sync(0xffffffffu, tm1, 2));
        const float mn0 = fmaxf(m0r, tm0), mn1 = fmaxf(m1r, tm1);
        const float c0f = fexp2((m0r - mn0) * L2E), c1f = fexp2((m1r - mn1) * L2E);
        m0r = mn0; m1r = mn1;
        const float mnl0 = mn0 * L2E, mnl1 = mn1 * L2E;
        float ls0 = 0.f, ls1 = 0.f;
#pragma unroll
        for (int nt = 0; nt < 8; nt++) {
            s[nt][0] = fexp2(fmaf(s[nt][0], L2E, -mnl0)); ls0 += s[nt][0];
            s[nt][1] = fexp2(fmaf(s[nt][1], L2E, -mnl0)); ls0 += s[nt][1];
            s[nt][2] = fexp2(fmaf(s[nt][2], L2E, -mnl1)); ls1 += s[nt][2];
            s[nt][3] = fexp2(fmaf(s[nt][3], L2E, -mnl1)); ls1 += s[nt][3];
        }
        ls0 += __shfl_xor_sync(0xffffffffu, ls0, 1);
        ls0 += __shfl_xor_sync(0xffffffffu, ls0, 2);
        ls1 += __shfl_xor_sync(0xffffffffu, ls1, 1);
        ls1 += __shfl_xor_sync(0xffffffffu, ls1, 2);
        l0 = l0 * c0f + ls0;
        l1 = l1 * c1f + ls1;
#pragma unroll
        for (int nt = 0; nt < 8; nt++) {
            o[nt][0] *= c0f; o[nt][1] *= c0f; o[nt][2] *= c1f; o[nt][3] *= c1f;
        }

        // O += P V — V fragments via ldmatrix.x4
#pragma unroll
        for (int kk = 0; kk < 4; kk++) {
            const int t0 = 2 * kk, t1 = 2 * kk + 1;
            unsigned pa[4], pl[4];
            pa[0] = packf(s[t0][0], s[t0][1]);
            pa[1] = packf(s[t0][2], s[t0][3]);
            pa[2] = packf(s[t1][0], s[t1][1]);
            pa[3] = packf(s[t1][2], s[t1][3]);
            pl[0] = packf(s[t0][0] - lo_f(pa[0]), s[t0][1] - hi_f(pa[0]));
            pl[1] = packf(s[t0][2] - lo_f(pa[1]), s[t0][3] - hi_f(pa[1]));
            pl[2] = packf(s[t1][0] - lo_f(pa[2]), s[t1][1] - hi_f(pa[2]));
            pl[3] = packf(s[t1][2] - lo_f(pa[3]), s[t1][3] - hi_f(pa[3]));
            const unsigned cof = kk * 16 * 2;
            unsigned vh_[8][2], vl_[8][2];
#pragma unroll
            for (int g = 0; g < 4; g++) {
                ldsm4(vh_[2 * g][0], vh_[2 * g][1], vh_[2 * g + 1][0], vh_[2 * g + 1][1],
                      vhA + g * (16 * 72 * 2) + cof);
                ldsm4(vl_[2 * g][0], vl_[2 * g][1], vl_[2 * g + 1][0], vl_[2 * g + 1][1],
                      vlA + g * (16 * 72 * 2) + cof);
            }
#pragma unroll
            for (int nt = 0; nt < 8; nt++) {
                mma_bf16(o[nt], pa, vh_[nt][0], vh_[nt][1]);
                mma_bf16(o[nt], pl, vh_[nt][0], vh_[nt][1]);
                mma_bf16(o[nt], pa, vl_[nt][0], vl_[nt][1]);
            }
        }
        __syncthreads();
    }

    // normalize + store split bf16 into [n][h*64+d]
    const float inv0 = 1.f / l0, inv1 = 1.f / l1;
    const int r = q0 + w * 16 + (lane >> 2);
#pragma unroll
    for (int nt = 0; nt < 8; nt++) {
        const int col = h * 64 + nt * 8 + (lane & 3) * 2;
        {
            float a = o[nt][0] * inv0, b = o[nt][1] * inv0;
            bf16 ha = __float2bfloat16_rn(a), hb = __float2bfloat16_rn(b);
            bf162 hh = __halves2bfloat162(ha, hb);
            *(unsigned*)&g_ah[(size_t)r * DIM + col] = *(unsigned*)&hh;
            *(unsigned*)&g_al[(size_t)r * DIM + col] =
                packf(a - __bfloat162float(ha), b - __bfloat162float(hb));
        }
        {
            float a = o[nt][2] * inv1, b = o[nt][3] * inv1;
            bf16 ha = __float2bfloat16_rn(a), hb = __float2bfloat16_rn(b);
            bf162 hh = __halves2bfloat162(ha, hb);
            *(unsigned*)&g_ah[(size_t)(r + 8) * DIM + col] = *(unsigned*)&hh;
            *(unsigned*)&g_al[(size_t)(r + 8) * DIM + col] =
                packf(a - __bfloat162float(ha), b - __bfloat162float(hb));
        }
    }
#undef FLASH_ISSUE
}

// ----------------------------------------------------------------------------
extern "C" void kernel_launch(void* const* d_in, const int* in_sizes, int n_in,
                              void* d_out, int out_size)
{
    (void)in_sizes; (void)n_in; (void)out_size;
    const float* x     = (const float*)d_in[0];
    const float* w_qkv = (const float*)d_in[1];
    const float* b_qkv = (const float*)d_in[2];
    const float* w_out = (const float*)d_in[3];
    const float* b_out = (const float*)d_in[4];
    float* out = (float*)d_out;

    bf16 *xh, *xl, *wqh, *wql, *woh, *wol, *ah, *al;
    cudaGetSymbolAddress((void**)&xh,  g_xh);  cudaGetSymbolAddress((void**)&xl,  g_xl);
    cudaGetSymbolAddress((void**)&wqh, g_wqh); cudaGetSymbolAddress((void**)&wql, g_wql);
    cudaGetSymbolAddress((void**)&woh, g_woh); cudaGetSymbolAddress((void**)&wol, g_wol);
    cudaGetSymbolAddress((void**)&ah,  g_ah);  cudaGetSymbolAddress((void**)&al,  g_al);

    const int gemm_smem = 2 * 4 * 128 * 40 * (int)sizeof(bf16);   // 81920
    cudaFuncSetAttribute(gemm_bf16x3<1, 3 * DIM, DIM>,
                         cudaFuncAttributeMaxDynamicSharedMemorySize, gemm_smem);
    cudaFuncSetAttribute(gemm_bf16x3<0, DIM, DIM>,
                         cudaFuncAttributeMaxDynamicSharedMemorySize, gemm_smem);

    // 0) fp32 -> split bf16
    split_kernel<<<(SEQ * DIM + 255) / 256, 256>>>(x, xh, xl, SEQ * DIM);
    split_kernel<<<(3 * DIM * DIM + 255) / 256, 256>>>(w_qkv, wqh, wql, 3 * DIM * DIM);
    split_kernel<<<(DIM * DIM + 255) / 256, 256>>>(w_out, woh, wol, DIM * DIM);

    // 1) QKV projection -> head-major Q,K + transposed V (split bf16)
    {
        dim3 grid(3 * DIM / 128, SEQ / 128);   // (18, 32)
        gemm_bf16x3<1, 3 * DIM, DIM><<<grid, 256, gemm_smem>>>(xh, xl, wqh, wql, b_qkv, nullptr);
    }

    // 2) flash attention: 73728B smem + 128-reg cap -> 2 CTAs/SM
    {
        const int smem = (2 * 2 * 64 * 72 * 2) * (int)sizeof(bf16); // 73728
        cudaFuncSetAttribute(flash_mma,
                             cudaFuncAttributeMaxDynamicSharedMemorySize, smem);
        dim3 grid(SEQ / 128, NH);              // (32, 12)
        flash_mma<<<grid, 256, smem>>>();
    }

    // 3) output projection
    {
        dim3 grid(DIM / 128, SEQ / 128);       // (6, 32)
        gemm_bf16x3<0, DIM, DIM><<<grid, 256, gemm_smem>>>(ah, al, woh, wol, b_out, out);
    }
}

// round 16
// speedup vs baseline: 1.0255x; 1.0255x over previous
#include <cuda_runtime.h>
#include <cuda_bf16.h>

#define SEQ 4096
#define DIM 768
#define NH  12
#define HD  64

typedef __nv_bfloat16  bf16;
typedef __nv_bfloat162 bf162;

// ---------------- scratch (static device arrays; no allocation) ----------------
__device__ bf16 g_xh [SEQ * DIM],      g_xl [SEQ * DIM];
__device__ bf16 g_wqh[3 * DIM * DIM],  g_wql[3 * DIM * DIM];
__device__ bf16 g_woh[DIM * DIM],      g_wol[DIM * DIM];
__device__ bf16 g_qkvh[2 * NH * SEQ * HD], g_qkvl[2 * NH * SEQ * HD]; // Q,K head-major
__device__ bf16 g_vth[NH * HD * SEQ],  g_vtl[NH * HD * SEQ];          // V transposed [h][d][key]
__device__ bf16 g_ah [SEQ * DIM],      g_al [SEQ * DIM];

// ---------------- helpers ----------------
__device__ __forceinline__ void mma_bf16(float d[4], const unsigned a[4],
                                         unsigned b0, unsigned b1) {
    asm volatile(
        "mma.sync.aligned.m16n8k16.row.col.f32.bf16.bf16.f32 "
        "{%0,%1,%2,%3}, {%4,%5,%6,%7}, {%8,%9}, {%0,%1,%2,%3};\n"
        : "+f"(d[0]), "+f"(d[1]), "+f"(d[2]), "+f"(d[3])
        : "r"(a[0]), "r"(a[1]), "r"(a[2]), "r"(a[3]), "r"(b0), "r"(b1));
}

__device__ __forceinline__ void ldsm4(unsigned& r0, unsigned& r1,
                                      unsigned& r2, unsigned& r3, unsigned a) {
    asm volatile("ldmatrix.sync.aligned.m8n8.x4.shared.b16 {%0,%1,%2,%3}, [%4];"
                 : "=r"(r0), "=r"(r1), "=r"(r2), "=r"(r3) : "r"(a));
}

__device__ __forceinline__ unsigned su32(const void* p) {
    return (unsigned)__cvta_generic_to_shared(p);
}

__device__ __forceinline__ void cpa16(void* s, const void* g) {
    unsigned sa = (unsigned)__cvta_generic_to_shared(s);
    asm volatile("cp.async.cg.shared.global [%0], [%1], 16;" :: "r"(sa), "l"(g));
}
__device__ __forceinline__ void cpa_commit() { asm volatile("cp.async.commit_group;"); }
template <int Npend>
__device__ __forceinline__ void cpa_wait() { asm volatile("cp.async.wait_group %0;" :: "n"(Npend)); }

__device__ __forceinline__ unsigned packf(float a, float b) {
    bf162 t = __floats2bfloat162_rn(a, b);
    return *reinterpret_cast<unsigned*>(&t);
}
__device__ __forceinline__ float lo_f(unsigned u) { return __uint_as_float(u << 16); }
__device__ __forceinline__ float hi_f(unsigned u) { return __uint_as_float(u & 0xffff0000u); }

// 2^x on the MUFU pipe (offloads the fma pipe; err ~2^-22)
__device__ __forceinline__ float fexp2(float x) {
    float y; asm("ex2.approx.f32 %0, %1;" : "=f"(y) : "f"(x)); return y;
}
#define L2E 1.4426950408889634f

// ---------------- fp32 -> bf16 hi/lo split ----------------
__global__ void split_kernel(const float* __restrict__ src,
                             bf16* __restrict__ h, bf16* __restrict__ l, int n) {
    int i = blockIdx.x * 256 + threadIdx.x;
    if (i < n) {
        float v  = src[i];
        bf16 hi = __float2bfloat16_rn(v);
        h[i] = hi;
        l[i] = __float2bfloat16_rn(v - __bfloat162float(hi));
    }
}

// ---------------- GEMM (NT), split-bf16 x3, cp.async + ldmatrix fragments ----------------
// BM=BN=128, BK=32, 256 threads, warps 4(m) x 2(n), warp tile 32x64.
// Fragments now via ldmatrix.x4: 12 LDSM per kk-step (was 48 scalar LDS.32).
// Stride-40 rows -> ldmatrix phase banks {0,20,8,28,16,4,24,12}*4: conflict-free.
template <int MODE, int N, int K>
__global__ void __launch_bounds__(256, 2)
gemm_bf16x3(const bf16* __restrict__ Agh, const bf16* __restrict__ Agl,
            const bf16* __restrict__ Bgh, const bf16* __restrict__ Bgl,
            const float* __restrict__ bias, float* __restrict__ C)
{
    extern __shared__ bf16 smg[];
    const int TS = 128 * 40;

    const int tid = threadIdx.x, lane = tid & 31, warp = tid >> 5;
    const int wm = warp >> 1, wn = warp & 1;
    const int m0 = blockIdx.y * 128, n0 = blockIdx.x * 128;

    // ldmatrix lane geometry
    const int lt = lane >> 3, lrr = lane & 7;
    // A matrices: (row+0,col+0)(row+8,col0)(row0,col+8)(row+8,col+8) -> a0..a3
    const unsigned lmA = (unsigned)((wm * 32 + (lt & 1) * 8 + lrr) * 40 + (lt >> 1) * 8) * 2;
    // B matrices: (row0,col0)(row0,col+8)(row+8,col0)(row+8,col+8) -> b[2g][0],b[2g][1],b[2g+1][0],b[2g+1][1]
    const unsigned lmB = (unsigned)((wn * 64 + (lt >> 1) * 8 + lrr) * 40 + (lt & 1) * 8) * 2;

    float acc[2][8][4];
#pragma unroll
    for (int mt = 0; mt < 2; mt++)
#pragma unroll
        for (int nt = 0; nt < 8; nt++)
#pragma unroll
            for (int e = 0; e < 4; e++) acc[mt][nt][e] = 0.f;

    const int lrow  = tid >> 2;
    const int lcol8 = (tid & 3) * 8;

#define GEMM_ISSUE(K0, S)                                                          \
    {                                                                              \
        bf16* b = smg + (S) * 4 * TS;                                              \
        _Pragma("unroll")                                                          \
        for (int i_ = 0; i_ < 2; i_++) {                                           \
            int row = lrow + 64 * i_;                                              \
            cpa16(b + row * 40 + lcol8,                                            \
                  Agh + (size_t)(m0 + row) * K + (K0) + lcol8);                    \
            cpa16(b + TS + row * 40 + lcol8,                                       \
                  Agl + (size_t)(m0 + row) * K + (K0) + lcol8);                    \
            cpa16(b + 2 * TS + row * 40 + lcol8,                                   \
                  Bgh + (size_t)(n0 + row) * K + (K0) + lcol8);                    \
            cpa16(b + 3 * TS + row * 40 + lcol8,                                   \
                  Bgl + (size_t)(n0 + row) * K + (K0) + lcol8);                    \
        }                                                                          \
        cpa_commit();                                                              \
    }

    GEMM_ISSUE(0, 0);

    const int KT = K / 32;
    for (int kt = 0; kt < KT; kt++) {
        if (kt + 1 < KT) { GEMM_ISSUE((kt + 1) * 32, (kt + 1) & 1); cpa_wait<1>(); }
        else             { cpa_wait<0>(); }
        __syncthreads();

        const bf16* As_h = smg + (kt & 1) * 4 * TS;
        const unsigned aH = su32(As_h)          + lmA;
        const unsigned aL = su32(As_h + TS)     + lmA;
        const unsigned bH = su32(As_h + 2 * TS) + lmB;
        const unsigned bL = su32(As_h + 3 * TS) + lmB;

#pragma unroll
        for (int kk = 0; kk < 2; kk++) {
            const unsigned coff = kk * 32;          // 16 elems * 2B
            unsigned ah[2][4], al_[2][4], bh[8][2], bl_[8][2];
#pragma unroll
            for (int mt = 0; mt < 2; mt++) {
                ldsm4(ah[mt][0], ah[mt][1], ah[mt][2], ah[mt][3],
                      aH + mt * (16 * 40 * 2) + coff);
                ldsm4(al_[mt][0], al_[mt][1], al_[mt][2], al_[mt][3],
                      aL + mt * (16 * 40 * 2) + coff);
            }
#pragma unroll
            for (int g = 0; g < 4; g++) {
                ldsm4(bh[2 * g][0], bh[2 * g][1], bh[2 * g + 1][0], bh[2 * g + 1][1],
                      bH + g * (16 * 40 * 2) + coff);
                ldsm4(bl_[2 * g][0], bl_[2 * g][1], bl_[2 * g + 1][0], bl_[2 * g + 1][1],
                      bL + g * (16 * 40 * 2) + coff);
            }
#pragma unroll
            for (int mt = 0; mt < 2; mt++)
#pragma unroll
                for (int nt = 0; nt < 8; nt++) {
                    mma_bf16(acc[mt][nt], ah[mt],  bh[nt][0],  bh[nt][1]);
                    mma_bf16(acc[mt][nt], ah[mt],  bl_[nt][0], bl_[nt][1]);
                    mma_bf16(acc[mt][nt], al_[mt], bh[nt][0],  bh[nt][1]);
                }
        }
        __syncthreads();
    }

    // epilogue
#pragma unroll
    for (int mt = 0; mt < 2; mt++) {
        const int m = m0 + wm * 32 + mt * 16 + (lane >> 2);
#pragma unroll
        for (int nt = 0; nt < 8; nt++) {
            const int n = n0 + wn * 64 + nt * 8 + (lane & 3) * 2;
            const float b0 = bias[n], b1 = bias[n + 1];
            float v[4];
            v[0] = acc[mt][nt][0] + b0; v[1] = acc[mt][nt][1] + b1;
            v[2] = acc[mt][nt][2] + b0; v[3] = acc[mt][nt][3] + b1;
            if (MODE == 0) {
                C[(size_t)m * N + n]           = v[0];
                C[(size_t)m * N + n + 1]       = v[1];
                C[(size_t)(m + 8) * N + n]     = v[2];
                C[(size_t)(m + 8) * N + n + 1] = v[3];
            } else {
#pragma unroll
                for (int e = 0; e < 4; e++) {
                    const int mm = m + ((e >> 1) & 1) * 8;
                    const int nn = n + (e & 1);
                    const int which = nn / DIM;
                    const int rem   = nn - which * DIM;   // h*64+d
                    bf16 hi = __float2bfloat16_rn(v[e]);
                    bf16 lo = __float2bfloat16_rn(v[e] - __bfloat162float(hi));
                    if (which == 2) {                     // V: transposed [h*64+d][key]
                        const size_t idx = (size_t)rem * SEQ + mm;
                        g_vth[idx] = hi; g_vtl[idx] = lo;
                    } else {                              // Q,K: [which][h][n][d]
                        const size_t idx =
                            (((size_t)which * NH + (rem >> 6)) * SEQ + mm) * HD + (rem & 63);
                        g_qkvh[idx] = hi; g_qkvl[idx] = lo;
                    }
                }
            }
        }
    }
#undef GEMM_ISSUE
}

// ---------------- Flash attention: 128q/256t, Q staged in K/V stage-0 buffers ----------------
// (proven 755us version: 73728B smem + 128-reg cap -> 2 CTAs/SM)
__global__ void __launch_bounds__(256, 2)
flash_mma()
{
    extern __shared__ char smraw[];
    bf16* Kbuf = (bf16*)smraw;              // [2 stages][Kh|Kl][64*72]
    bf16* Vbuf = Kbuf + 2 * 2 * 64 * 72;    // [2 stages][Vth|Vtl][64*72]  (d, key)
    const int KTS = 64 * 72;
    bf16* Qh = Kbuf;                        // Q staged in stage0 of Kbuf
    bf16* Ql = Vbuf;                        // Q-low staged in stage0 of Vbuf

    const int h  = blockIdx.y;
    const int q0 = blockIdx.x * 128;
    const int tid = threadIdx.x, lane = tid & 31, w = tid >> 5;

    const bf16* Qg_h = g_qkvh + ((size_t)(0 * NH + h) * SEQ + q0) * HD;
    const bf16* Qg_l = g_qkvl + ((size_t)(0 * NH + h) * SEQ + q0) * HD;
    const bf16* Kg_h = g_qkvh + (size_t)(NH + h) * SEQ * HD;
    const bf16* Kg_l = g_qkvl + (size_t)(NH + h) * SEQ * HD;
    const bf16* Vg_h = g_vth + (size_t)h * HD * SEQ;   // [d][key]
    const bf16* Vg_l = g_vtl + (size_t)h * HD * SEQ;

    const int lt = lane >> 3, lrr = lane & 7;
    const unsigned lm_off = (((lt >> 1) * 8 + lrr) * 72 + (lt & 1) * 8) * 2;

    const int frow  = tid >> 3;        // 0..31
    const int fcol8 = (tid & 7) * 8;   // 0..56

#define FLASH_ISSUE(KT_, S)                                                        \
    {                                                                              \
        bf16* kb = Kbuf + (S) * 2 * KTS;                                           \
        bf16* vb = Vbuf + (S) * 2 * KTS;                                           \
        _Pragma("unroll")                                                          \
        for (int i_ = 0; i_ < 2; i_++) {                                           \
            int row = frow + 32 * i_;                                              \
            cpa16(kb + row * 72 + fcol8,                                           \
                  Kg_h + (size_t)((KT_) * 64 + row) * 64 + fcol8);                 \
            cpa16(kb + KTS + row * 72 + fcol8,                                     \
                  Kg_l + (size_t)((KT_) * 64 + row) * 64 + fcol8);                 \
            cpa16(vb + row * 72 + fcol8,                                           \
                  Vg_h + (size_t)row * SEQ + (KT_) * 64 + fcol8);                  \
            cpa16(vb + KTS + row * 72 + fcol8,                                     \
                  Vg_l + (size_t)row * SEQ + (KT_) * 64 + fcol8);                  \
        }                                                                          \
        cpa_commit();                                                              \
    }

    // --- stage Q in the (not yet used) stage-0 K/V buffers, pre-scaled by 1/8 ---
    const bf162 sc = __floats2bfloat162_rn(0.125f, 0.125f);
#pragma unroll
    for (int i = 0; i < 4; i++) {
        int c = tid + 256 * i;
        int row = c >> 3, col8 = (c & 7) * 8;
        uint4 vh = *(const uint4*)&Qg_h[row * 64 + col8];
        uint4 vl = *(const uint4*)&Qg_l[row * 64 + col8];
        bf162* ph = (bf162*)&vh;
        bf162* pl = (bf162*)&vl;
#pragma unroll
        for (int e = 0; e < 4; e++) { ph[e] = __hmul2(ph[e], sc); pl[e] = __hmul2(pl[e], sc); }
        *(uint4*)&Qh[row * 72 + col8] = vh;
        *(uint4*)&Ql[row * 72 + col8] = vl;
    }
    __syncthreads();

    // Q fragments -> registers (persist across all key tiles)
    unsigned qfh[4][4], qfl[4][4];
    {
        const int r = w * 16 + (lane >> 2);
#pragma unroll
        for (int kk = 0; kk < 4; kk++) {
            const int c0 = kk * 16 + (lane & 3) * 2;
            qfh[kk][0] = *(unsigned*)&Qh[r * 72 + c0];
            qfh[kk][1] = *(unsigned*)&Qh[(r + 8) * 72 + c0];
            qfh[kk][2] = *(unsigned*)&Qh[r * 72 + c0 + 8];
            qfh[kk][3] = *(unsigned*)&Qh[(r + 8) * 72 + c0 + 8];
            qfl[kk][0] = *(unsigned*)&Ql[r * 72 + c0];
            qfl[kk][1] = *(unsigned*)&Ql[(r + 8) * 72 + c0];
            qfl[kk][2] = *(unsigned*)&Ql[r * 72 + c0 + 8];
            qfl[kk][3] = *(unsigned*)&Ql[(r + 8) * 72 + c0 + 8];
        }
    }
    __syncthreads();   // all Q reads done before the pipeline overwrites stage 0

    FLASH_ISSUE(0, 0);

    float o[8][4];
#pragma unroll
    for (int nt = 0; nt < 8; nt++)
#pragma unroll
        for (int e = 0; e < 4; e++) o[nt][e] = 0.f;
    float m0r = -1e30f, m1r = -1e30f, l0 = 0.f, l1 = 0.f;

    const int NKT = SEQ / 64;
    for (int kt = 0; kt < NKT; kt++) {
        if (kt + 1 < NKT) { FLASH_ISSUE(kt + 1, (kt + 1) & 1); cpa_wait<1>(); }
        else              { cpa_wait<0>(); }
        __syncthreads();

        const bf16* Kh = Kbuf + (kt & 1) * 2 * KTS;
        const bf16* Kl = Kh + KTS;
        const bf16* Vh = Vbuf + (kt & 1) * 2 * KTS;
        const bf16* Vl = Vh + KTS;
        const unsigned khA = su32(Kh) + lm_off;
        const unsigned klA = su32(Kl) + lm_off;
        const unsigned vhA = su32(Vh) + lm_off;
        const unsigned vlA = su32(Vl) + lm_off;

        // S = (Q/8) K^T — fragments via ldmatrix.x4
        float s[8][4];
#pragma unroll
        for (int nt = 0; nt < 8; nt++)
#pragma unroll
            for (int e = 0; e < 4; e++) s[nt][e] = 0.f;
#pragma unroll
        for (int kk = 0; kk < 4; kk++) {
            const unsigned cof = kk * 16 * 2;
            unsigned bh[8][2], bl_[8][2];
#pragma unroll
            for (int g = 0; g < 4; g++) {
                ldsm4(bh[2 * g][0], bh[2 * g][1], bh[2 * g + 1][0], bh[2 * g + 1][1],
                      khA + g * (16 * 72 * 2) + cof);
                ldsm4(bl_[2 * g][0], bl_[2 * g][1], bl_[2 * g + 1][0], bl_[2 * g + 1][1],
                      klA + g * (16 * 72 * 2) + cof);
            }
#pragma unroll
            for (int nt = 0; nt < 8; nt++) {
                mma_bf16(s[nt], qfh[kk], bh[nt][0], bh[nt][1]);
                mma_bf16(s[nt], qfl[kk], bh[nt][0], bh[nt][1]);
                mma_bf16(s[nt], qfh[kk], bl_[nt][0], bl_[nt][1]);
            }
        }

        // online softmax via MUFU ex2 (rows r=lane/4 and r+8); reduce across lane%4
        float tm0 = -1e30f, tm1 = -1e30f;
#pragma unroll
        for (int nt = 0; nt < 8; nt++) {
            tm0 = fmaxf(tm0, fmaxf(s[nt][0], s[nt][1]));
            tm1 = fmaxf(tm1, fmaxf(s[nt][2], s[nt][3]));
        }
        tm0 = fmaxf(tm0, __shfl_xor_sync(0xffffffffu, tm0, 1));
        tm0 = fmaxf(tm0, __shfl_xor_sync(0xffffffffu, tm0, 2));
        tm1 = fmaxf(tm1, __shfl_xor_sync(0xffffffffu, tm1, 1));
        tm1 = fmaxf(tm1, __shfl_xor_sync(0xffffffffu, tm1, 2));
        const float mn0 = fmaxf(m0r, tm0), mn1 = fmaxf(m1r, tm1);
        const float c0f = fexp2((m0r - mn0) * L2E), c1f = fexp2((m1r - mn1) * L2E);
        m0r = mn0; m1r = mn1;
        const float mnl0 = mn0 * L2E, mnl1 = mn1 * L2E;
        float ls0 = 0.f, ls1 = 0.f;
#pragma unroll
        for (int nt = 0; nt < 8; nt++) {
            s[nt][0] = fexp2(fmaf(s[nt][0], L2E, -mnl0)); ls0 += s[nt][0];
            s[nt][1] = fexp2(fmaf(s[nt][1], L2E, -mnl0)); ls0 += s[nt][1];
            s[nt][2] = fexp2(fmaf(s[nt][2], L2E, -mnl1)); ls1 += s[nt][2];
            s[nt][3] = fexp2(fmaf(s[nt][3], L2E, -mnl1)); ls1 += s[nt][3];
        }
        ls0 += __shfl_xor_sync(0xffffffffu, ls0, 1);
        ls0 += __shfl_xor_sync(0xffffffffu, ls0, 2);
        ls1 += __shfl_xor_sync(0xffffffffu, ls1, 1);
        ls1 += __shfl_xor_sync(0xffffffffu, ls1, 2);
        l0 = l0 * c0f + ls0;
        l1 = l1 * c1f + ls1;
#pragma unroll
        for (int nt = 0; nt < 8; nt++) {
            o[nt][0] *= c0f; o[nt][1] *= c0f; o[nt][2] *= c1f; o[nt][3] *= c1f;
        }

        // O += P V — V fragments via ldmatrix.x4
#pragma unroll
        for (int kk = 0; kk < 4; kk++) {
            const int t0 = 2 * kk, t1 = 2 * kk + 1;
            unsigned pa[4], pl[4];
            pa[0] = packf(s[t0][0], s[t0][1]);
            pa[1] = packf(s[t0][2], s[t0][3]);
            pa[2] = packf(s[t1][0], s[t1][1]);
            pa[3] = packf(s[t1][2], s[t1][3]);
            pl[0] = packf(s[t0][0] - lo_f(pa[0]), s[t0][1] - hi_f(pa[0]));
            pl[1] = packf(s[t0][2] - lo_f(pa[1]), s[t0][3] - hi_f(pa[1]));
            pl[2] = packf(s[t1][0] - lo_f(pa[2]), s[t1][1] - hi_f(pa[2]));
            pl[3] = packf(s[t1][2] - lo_f(pa[3]), s[t1][3] - hi_f(pa[3]));
            const unsigned cof = kk * 16 * 2;
            unsigned vh_[8][2], vl_[8][2];
#pragma unroll
            for (int g = 0; g < 4; g++) {
                ldsm4(vh_[2 * g][0], vh_[2 * g][1], vh_[2 * g + 1][0], vh_[2 * g + 1][1],
                      vhA + g * (16 * 72 * 2) + cof);
                ldsm4(vl_[2 * g][0], vl_[2 * g][1], vl_[2 * g + 1][0], vl_[2 * g + 1][1],
                      vlA + g * (16 * 72 * 2) + cof);
            }
#pragma unroll
            for (int nt = 0; nt < 8; nt++) {
                mma_bf16(o[nt], pa, vh_[nt][0], vh_[nt][1]);
                mma_bf16(o[nt], pl, vh_[nt][0], vh_[nt][1]);
                mma_bf16(o[nt], pa, vl_[nt][0], vl_[nt][1]);
            }
        }
        __syncthreads();
    }

    // normalize + store split bf16 into [n][h*64+d]
    const float inv0 = 1.f / l0, inv1 = 1.f / l1;
    const int r = q0 + w * 16 + (lane >> 2);
#pragma unroll
    for (int nt = 0; nt < 8; nt++) {
        const int col = h * 64 + nt * 8 + (lane & 3) * 2;
        {
            float a = o[nt][0] * inv0, b = o[nt][1] * inv0;
            bf16 ha = __float2bfloat16_rn(a), hb = __float2bfloat16_rn(b);
            bf162 hh = __halves2bfloat162(ha, hb);
            *(unsigned*)&g_ah[(size_t)r * DIM + col] = *(unsigned*)&hh;
            *(unsigned*)&g_al[(size_t)r * DIM + col] =
                packf(a - __bfloat162float(ha), b - __bfloat162float(hb));
        }
        {
            float a = o[nt][2] * inv1, b = o[nt][3] * inv1;
            bf16 ha = __float2bfloat16_rn(a), hb = __float2bfloat16_rn(b);
            bf162 hh = __halves2bfloat162(ha, hb);
            *(unsigned*)&g_ah[(size_t)(r + 8) * DIM + col] = *(unsigned*)&hh;
            *(unsigned*)&g_al[(size_t)(r + 8) * DIM + col] =
                packf(a - __bfloat162float(ha), b - __bfloat162float(hb));
        }
    }
#undef FLASH_ISSUE
}

// ----------------------------------------------------------------------------
extern "C" void kernel_launch(void* const* d_in, const int* in_sizes, int n_in,
                              void* d_out, int out_size)
{
    (void)in_sizes; (void)n_in; (void)out_size;
    const float* x     = (const float*)d_in[0];
    const float* w_qkv = (const float*)d_in[1];
    const float* b_qkv = (const float*)d_in[2];
    const float* w_out = (const float*)d_in[3];
    const float* b_out = (const float*)d_in[4];
    float* out = (float*)d_out;

    bf16 *xh, *xl, *wqh, *wql, *woh, *wol, *ah, *al;
    cudaGetSymbolAddress((void**)&xh,  g_xh);  cudaGetSymbolAddress((void**)&xl,  g_xl);
    cudaGetSymbolAddress((void**)&wqh, g_wqh); cudaGetSymbolAddress((void**)&wql, g_wql);
    cudaGetSymbolAddress((void**)&woh, g_woh); cudaGetSymbolAddress((void**)&wol, g_wol);
    cudaGetSymbolAddress((void**)&ah,  g_ah);  cudaGetSymbolAddress((void**)&al,  g_al);

    const int gemm_smem = 2 * 4 * 128 * 40 * (int)sizeof(bf16);   // 81920
    cudaFuncSetAttribute(gemm_bf16x3<1, 3 * DIM, DIM>,
                         cudaFuncAttributeMaxDynamicSharedMemorySize, gemm_smem);
    cudaFuncSetAttribute(gemm_bf16x3<0, DIM, DIM>,
                         cudaFuncAttributeMaxDynamicSharedMemorySize, gemm_smem);

    // 0) fp32 -> split bf16
    split_kernel<<<(SEQ * DIM + 255) / 256, 256>>>(x, xh, xl, SEQ * DIM);
    split_kernel<<<(3 * DIM * DIM + 255) / 256, 256>>>(w_qkv, wqh, wql, 3 * DIM * DIM);
    split_kernel<<<(DIM * DIM + 255) / 256, 256>>>(w_out, woh, wol, DIM * DIM);

    // 1) QKV projection -> head-major Q,K + transposed V (split bf16)
    {
        dim3 grid(3 * DIM / 128, SEQ / 128);   // (18, 32)
        gemm_bf16x3<1, 3 * DIM, DIM><<<grid, 256, gemm_smem>>>(xh, xl, wqh, wql, b_qkv, nullptr);
    }

    // 2) flash attention: 73728B smem + 128-reg cap -> 2 CTAs/SM
    {
        const int smem = (2 * 2 * 64 * 72 * 2) * (int)sizeof(bf16); // 73728
        cudaFuncSetAttribute(flash_mma,
                             cudaFuncAttributeMaxDynamicSharedMemorySize, smem);
        dim3 grid(SEQ / 128, NH);              // (32, 12)
        flash_mma<<<grid, 256, smem>>>();
    }

    // 3) output projection
    {
        dim3 grid(DIM / 128, SEQ / 128);       // (6, 32)
        gemm_bf16x3<0, DIM, DIM><<<grid, 256, gemm_smem>>>(ah, al, woh, wol, b_out, out);
    }
}

// round 17
// speedup vs baseline: 1.4247x; 1.3893x over previous
#include <cuda_runtime.h>
#include <cuda_fp16.h>

#define SEQ 4096
#define DIM 768
#define NH  12
#define HD  64

typedef __half  f16;
typedef __half2 f162;

// ---------------- scratch (static device arrays; no allocation) ----------------
__device__ f16 g_xh [SEQ * DIM], g_xl [SEQ * DIM];
__device__ f16 g_wq [3 * DIM * DIM];
__device__ f16 g_wo [DIM * DIM];
__device__ f16 g_qh [NH * SEQ * HD], g_ql [NH * SEQ * HD];  // Q split, head-major
__device__ f16 g_k  [NH * SEQ * HD];                         // K single, head-major
__device__ f16 g_vt [NH * HD * SEQ];                         // V single, transposed [h][d][key]
__device__ f16 g_ah [SEQ * DIM], g_al [SEQ * DIM];           // attn out split

// ---------------- helpers ----------------
__device__ __forceinline__ void mma_f16(float d[4], const unsigned a[4],
                                        unsigned b0, unsigned b1) {
    asm volatile(
        "mma.sync.aligned.m16n8k16.row.col.f32.f16.f16.f32 "
        "{%0,%1,%2,%3}, {%4,%5,%6,%7}, {%8,%9}, {%0,%1,%2,%3};\n"
        : "+f"(d[0]), "+f"(d[1]), "+f"(d[2]), "+f"(d[3])
        : "r"(a[0]), "r"(a[1]), "r"(a[2]), "r"(a[3]), "r"(b0), "r"(b1));
}

__device__ __forceinline__ void ldsm4(unsigned& r0, unsigned& r1,
                                      unsigned& r2, unsigned& r3, unsigned a) {
    asm volatile("ldmatrix.sync.aligned.m8n8.x4.shared.b16 {%0,%1,%2,%3}, [%4];"
                 : "=r"(r0), "=r"(r1), "=r"(r2), "=r"(r3) : "r"(a));
}

__device__ __forceinline__ unsigned su32(const void* p) {
    return (unsigned)__cvta_generic_to_shared(p);
}

__device__ __forceinline__ void cpa16(void* s, const void* g) {
    unsigned sa = (unsigned)__cvta_generic_to_shared(s);
    asm volatile("cp.async.cg.shared.global [%0], [%1], 16;" :: "r"(sa), "l"(g));
}
__device__ __forceinline__ void cpa_commit() { asm volatile("cp.async.commit_group;"); }
template <int Npend>
__device__ __forceinline__ void cpa_wait() { asm volatile("cp.async.wait_group %0;" :: "n"(Npend)); }

__device__ __forceinline__ unsigned packh2(float a, float b) {
    f162 t = __floats2half2_rn(a, b);
    return *reinterpret_cast<unsigned*>(&t);
}
__device__ __forceinline__ float lo_h(unsigned u) { f162 h = *(f162*)&u; return __low2float(h); }
__device__ __forceinline__ float hi_h(unsigned u) { f162 h = *(f162*)&u; return __high2float(h); }

// 2^x on the MUFU pipe
__device__ __forceinline__ float fexp2(float x) {
    float y; asm("ex2.approx.f32 %0, %1;" : "=f"(y) : "f"(x)); return y;
}
#define L2E 1.4426950408889634f

// ---------------- fp32 -> fp16 hi/lo split  /  single round ----------------
__global__ void split_kernel(const float* __restrict__ src,
                             f16* __restrict__ h, f16* __restrict__ l, int n) {
    int i = blockIdx.x * 256 + threadIdx.x;
    if (i < n) {
        float v  = src[i];
        f16 hi = __float2half_rn(v);
        h[i] = hi;
        l[i] = __float2half_rn(v - __half2float(hi));
    }
}
__global__ void round_kernel(const float* __restrict__ src, f16* __restrict__ h, int n) {
    int i = blockIdx.x * 256 + threadIdx.x;
    if (i < n) h[i] = __float2half_rn(src[i]);
}

// ---------------- GEMM (NT), split-fp16 x2, cp.async + ldmatrix ----------------
// C = (Ah+Al) Bh^T + bias ; A split fp16, B single fp16. 2 mma passes per fragment.
// BM=BN=128, BK=32, 256 threads, warps 4(m) x 2(n), warp tile 32x64.
template <int MODE, int N, int K>
__global__ void __launch_bounds__(256, 2)
gemm_f16x2(const f16* __restrict__ Agh, const f16* __restrict__ Agl,
           const f16* __restrict__ Bg,
           const float* __restrict__ bias, float* __restrict__ C)
{
    extern __shared__ f16 smg[];
    const int TS = 128 * 40;

    const int tid = threadIdx.x, lane = tid & 31, warp = tid >> 5;
    const int wm = warp >> 1, wn = warp & 1;
    const int m0 = blockIdx.y * 128, n0 = blockIdx.x * 128;

    const int lt = lane >> 3, lrr = lane & 7;
    const unsigned lmA = (unsigned)((wm * 32 + (lt & 1) * 8 + lrr) * 40 + (lt >> 1) * 8) * 2;
    const unsigned lmB = (unsigned)((wn * 64 + (lt >> 1) * 8 + lrr) * 40 + (lt & 1) * 8) * 2;

    float acc[2][8][4];
#pragma unroll
    for (int mt = 0; mt < 2; mt++)
#pragma unroll
        for (int nt = 0; nt < 8; nt++)
#pragma unroll
            for (int e = 0; e < 4; e++) acc[mt][nt][e] = 0.f;

    const int lrow  = tid >> 2;
    const int lcol8 = (tid & 3) * 8;

#define GEMM_ISSUE(K0, S)                                                          \
    {                                                                              \
        f16* b = smg + (S) * 3 * TS;                                               \
        _Pragma("unroll")                                                          \
        for (int i_ = 0; i_ < 2; i_++) {                                           \
            int row = lrow + 64 * i_;                                              \
            cpa16(b + row * 40 + lcol8,                                            \
                  Agh + (size_t)(m0 + row) * K + (K0) + lcol8);                    \
            cpa16(b + TS + row * 40 + lcol8,                                       \
                  Agl + (size_t)(m0 + row) * K + (K0) + lcol8);                    \
            cpa16(b + 2 * TS + row * 40 + lcol8,                                   \
                  Bg  + (size_t)(n0 + row) * K + (K0) + lcol8);                    \
        }                                                                          \
        cpa_commit();                                                              \
    }

    GEMM_ISSUE(0, 0);

    const int KT = K / 32;
    for (int kt = 0; kt < KT; kt++) {
        if (kt + 1 < KT) { GEMM_ISSUE((kt + 1) * 32, (kt + 1) & 1); cpa_wait<1>(); }
        else             { cpa_wait<0>(); }
        __syncthreads();

        const f16* As_h = smg + (kt & 1) * 3 * TS;
        const unsigned aH = su32(As_h)          + lmA;
        const unsigned aL = su32(As_h + TS)     + lmA;
        const unsigned bH = su32(As_h + 2 * TS) + lmB;

#pragma unroll
        for (int kk = 0; kk < 2; kk++) {
            const unsigned coff = kk * 32;
            unsigned ah[2][4], al_[2][4], bh[8][2];
#pragma unroll
            for (int mt = 0; mt < 2; mt++) {
                ldsm4(ah[mt][0], ah[mt][1], ah[mt][2], ah[mt][3],
                      aH + mt * (16 * 40 * 2) + coff);
                ldsm4(al_[mt][0], al_[mt][1], al_[mt][2], al_[mt][3],
                      aL + mt * (16 * 40 * 2) + coff);
            }
#pragma unroll
            for (int g = 0; g < 4; g++) {
                ldsm4(bh[2 * g][0], bh[2 * g][1], bh[2 * g + 1][0], bh[2 * g + 1][1],
                      bH + g * (16 * 40 * 2) + coff);
            }
#pragma unroll
            for (int mt = 0; mt < 2; mt++)
#pragma unroll
                for (int nt = 0; nt < 8; nt++) {
                    mma_f16(acc[mt][nt], ah[mt],  bh[nt][0], bh[nt][1]);
                    mma_f16(acc[mt][nt], al_[mt], bh[nt][0], bh[nt][1]);
                }
        }
        __syncthreads();
    }

    // epilogue
#pragma unroll
    for (int mt = 0; mt < 2; mt++) {
        const int m = m0 + wm * 32 + mt * 16 + (lane >> 2);
#pragma unroll
        for (int nt = 0; nt < 8; nt++) {
            const int n = n0 + wn * 64 + nt * 8 + (lane & 3) * 2;
            const float b0 = bias[n], b1 = bias[n + 1];
            float v[4];
            v[0] = acc[mt][nt][0] + b0; v[1] = acc[mt][nt][1] + b1;
            v[2] = acc[mt][nt][2] + b0; v[3] = acc[mt][nt][3] + b1;
            if (MODE == 0) {
                C[(size_t)m * N + n]           = v[0];
                C[(size_t)m * N + n + 1]       = v[1];
                C[(size_t)(m + 8) * N + n]     = v[2];
                C[(size_t)(m + 8) * N + n + 1] = v[3];
            } else {
#pragma unroll
                for (int e = 0; e < 4; e++) {
                    const int mm = m + ((e >> 1) & 1) * 8;
                    const int nn = n + (e & 1);
                    const int which = nn / DIM;
                    const int rem   = nn - which * DIM;   // h*64+d
                    const int head  = rem >> 6, dd = rem & 63;
                    if (which == 0) {                     // Q: split fp16
                        const size_t idx = ((size_t)head * SEQ + mm) * HD + dd;
                        f16 hi = __float2half_rn(v[e]);
                        g_qh[idx] = hi;
                        g_ql[idx] = __float2half_rn(v[e] - __half2float(hi));
                    } else if (which == 1) {              // K: single fp16
                        const size_t idx = ((size_t)head * SEQ + mm) * HD + dd;
                        g_k[idx] = __float2half_rn(v[e]);
                    } else {                              // V: single, transposed
                        g_vt[(size_t)rem * SEQ + mm] = __float2half_rn(v[e]);
                    }
                }
            }
        }
    }
#undef GEMM_ISSUE
}

// ---------------- Flash attention: split-fp16 x2, ldmatrix + MUFU exp ----------------
// CTA 128q/256t; K,V single fp16 (1 tile each per stage); Q split in registers;
// P split in registers. smem = 4*64*72*2 = 36864 B -> 2+ CTAs/SM.
__global__ void __launch_bounds__(256, 2)
flash_mma()
{
    extern __shared__ char smraw[];
    f16* Kbuf = (f16*)smraw;                // [2 stages][64*72]
    f16* Vbuf = Kbuf + 2 * 64 * 72;         // [2 stages][64*72]  (d, key)
    const int KTS = 64 * 72;
    f16* Qh = Kbuf;                         // Q staged across both K stages (128*72)
    f16* Ql = Vbuf;                         // Q-low across both V stages

    const int h  = blockIdx.y;
    const int q0 = blockIdx.x * 128;
    const int tid = threadIdx.x, lane = tid & 31, w = tid >> 5;

    const f16* Qg_h = g_qh + ((size_t)h * SEQ + q0) * HD;
    const f16* Qg_l = g_ql + ((size_t)h * SEQ + q0) * HD;
    const f16* Kg   = g_k  + (size_t)h * SEQ * HD;
    const f16* Vg   = g_vt + (size_t)h * HD * SEQ;   // [d][key]

    const int lt = lane >> 3, lrr = lane & 7;
    const unsigned lm_off = (((lt >> 1) * 8 + lrr) * 72 + (lt & 1) * 8) * 2;

    const int frow  = tid >> 3;        // 0..31
    const int fcol8 = (tid & 7) * 8;   // 0..56

#define FLASH_ISSUE(KT_, S)                                                        \
    {                                                                              \
        f16* kb = Kbuf + (S) * KTS;                                                \
        f16* vb = Vbuf + (S) * KTS;                                                \
        _Pragma("unroll")                                                          \
        for (int i_ = 0; i_ < 2; i_++) {                                           \
            int row = frow + 32 * i_;                                              \
            cpa16(kb + row * 72 + fcol8,                                           \
                  Kg + (size_t)((KT_) * 64 + row) * 64 + fcol8);                   \
            cpa16(vb + row * 72 + fcol8,                                           \
                  Vg + (size_t)row * SEQ + (KT_) * 64 + fcol8);                    \
        }                                                                          \
        cpa_commit();                                                              \
    }

    // --- stage Q (pre-scaled by 1/8, exact in fp16) in the not-yet-used K/V buffers ---
    const f162 sc = __floats2half2_rn(0.125f, 0.125f);
#pragma unroll
    for (int i = 0; i < 4; i++) {
        int c = tid + 256 * i;
        int row = c >> 3, col8 = (c & 7) * 8;
        uint4 vh = *(const uint4*)&Qg_h[row * 64 + col8];
        uint4 vl = *(const uint4*)&Qg_l[row * 64 + col8];
        f162* ph = (f162*)&vh;
        f162* pl = (f162*)&vl;
#pragma unroll
        for (int e = 0; e < 4; e++) { ph[e] = __hmul2(ph[e], sc); pl[e] = __hmul2(pl[e], sc); }
        *(uint4*)&Qh[row * 72 + col8] = vh;
        *(uint4*)&Ql[row * 72 + col8] = vl;
    }
    __syncthreads();

    // Q fragments -> registers (persist across all key tiles)
    unsigned qfh[4][4], qfl[4][4];
    {
        const int r = w * 16 + (lane >> 2);
#pragma unroll
        for (int kk = 0; kk < 4; kk++) {
            const int c0 = kk * 16 + (lane & 3) * 2;
            qfh[kk][0] = *(unsigned*)&Qh[r * 72 + c0];
            qfh[kk][1] = *(unsigned*)&Qh[(r + 8) * 72 + c0];
            qfh[kk][2] = *(unsigned*)&Qh[r * 72 + c0 + 8];
            qfh[kk][3] = *(unsigned*)&Qh[(r + 8) * 72 + c0 + 8];
            qfl[kk][0] = *(unsigned*)&Ql[r * 72 + c0];
            qfl[kk][1] = *(unsigned*)&Ql[(r + 8) * 72 + c0];
            qfl[kk][2] = *(unsigned*)&Ql[r * 72 + c0 + 8];
            qfl[kk][3] = *(unsigned*)&Ql[(r + 8) * 72 + c0 + 8];
        }
    }
    __syncthreads();   // Q reads done before the pipeline overwrites the buffers

    FLASH_ISSUE(0, 0);

    float o[8][4];
#pragma unroll
    for (int nt = 0; nt < 8; nt++)
#pragma unroll
        for (int e = 0; e < 4; e++) o[nt][e] = 0.f;
    float m0r = -1e30f, m1r = -1e30f, l0 = 0.f, l1 = 0.f;

    const int NKT = SEQ / 64;
    for (int kt = 0; kt < NKT; kt++) {
        if (kt + 1 < NKT) { FLASH_ISSUE(kt + 1, (kt + 1) & 1); cpa_wait<1>(); }
        else              { cpa_wait<0>(); }
        __syncthreads();

        const f16* Kh = Kbuf + (kt & 1) * KTS;
        const f16* Vh = Vbuf + (kt & 1) * KTS;
        const unsigned khA = su32(Kh) + lm_off;
        const unsigned vhA = su32(Vh) + lm_off;

        // S = (Q/8) K^T — 2 passes (Qh, Ql) x single-K fragments
        float s[8][4];
#pragma unroll
        for (int nt = 0; nt < 8; nt++)
#pragma unroll
            for (int e = 0; e < 4; e++) s[nt][e] = 0.f;
#pragma unroll
        for (int kk = 0; kk < 4; kk++) {
            const unsigned cof = kk * 16 * 2;
            unsigned bh[8][2];
#pragma unroll
            for (int g = 0; g < 4; g++) {
                ldsm4(bh[2 * g][0], bh[2 * g][1], bh[2 * g + 1][0], bh[2 * g + 1][1],
                      khA + g * (16 * 72 * 2) + cof);
            }
#pragma unroll
            for (int nt = 0; nt < 8; nt++) {
                mma_f16(s[nt], qfh[kk], bh[nt][0], bh[nt][1]);
                mma_f16(s[nt], qfl[kk], bh[nt][0], bh[nt][1]);
            }
        }

        // online softmax via MUFU ex2 (rows r=lane/4 and r+8); reduce across lane%4
        float tm0 = -1e30f, tm1 = -1e30f;
#pragma unroll
        for (int nt = 0; nt < 8; nt++) {
            tm0 = fmaxf(tm0, fmaxf(s[nt][0], s[nt][1]));
            tm1 = fmaxf(tm1, fmaxf(s[nt][2], s[nt][3]));
        }
        tm0 = fmaxf(tm0, __shfl_xor_sync(0xffffffffu, tm0, 1));
        tm0 = fmaxf(tm0, __shfl_xor_sync(0xffffffffu, tm0, 2));
        tm1 = fmaxf(tm1, __shfl_xor_sync(0xffffffffu, tm1, 1));
        tm1 = fmaxf(tm1, __shfl_xor_sync(0xffffffffu, tm1, 2));
        const float mn0 = fmaxf(m0r, tm0), mn1 = fmaxf(m1r, tm1);
        const float c0f = fexp2((m0r - mn0) * L2E), c1f = fexp2((m1r - mn1) * L2E);
        m0r = mn0; m1r = mn1;
        const float mnl0 = mn0 * L2E, mnl1 = mn1 * L2E;
        float ls0 = 0.f, ls1 = 0.f;
#pragma unroll
        for (int nt = 0; nt < 8; nt++) {
            s[nt][0] = fexp2(fmaf(s[nt][0], L2E, -mnl0)); ls0 += s[nt][0];
            s[nt][1] = fexp2(fmaf(s[nt][1], L2E, -mnl0)); ls0 += s[nt][1];
            s[nt][2] = fexp2(fmaf(s[nt][2], L2E, -mnl1)); ls1 += s[nt][2];
            s[nt][3] = fexp2(fmaf(s[nt][3], L2E, -mnl1)); ls1 += s[nt][3];
        }
        ls0 += __shfl_xor_sync(0xffffffffu, ls0, 1);
        ls0 += __shfl_xor_sync(0xffffffffu, ls0, 2);
        ls1 += __shfl_xor_sync(0xffffffffu, ls1, 1);
        ls1 += __shfl_xor_sync(0xffffffffu, ls1, 2);
        l0 = l0 * c0f + ls0;
        l1 = l1 * c1f + ls1;
#pragma unroll
        for (int nt = 0; nt < 8; nt++) {
            o[nt][0] *= c0f; o[nt][1] *= c0f; o[nt][2] *= c1f; o[nt][3] *= c1f;
        }

        // O += P V — P split fp16 (Ph + Pl), V single
#pragma unroll
        for (int kk = 0; kk < 4; kk++) {
            const int t0 = 2 * kk, t1 = 2 * kk + 1;
            unsigned pa[4], pl[4];
            pa[0] = packh2(s[t0][0], s[t0][1]);
            pa[1] = packh2(s[t0][2], s[t0][3]);
            pa[2] = packh2(s[t1][0], s[t1][1]);
            pa[3] = packh2(s[t1][2], s[t1][3]);
            pl[0] = packh2(s[t0][0] - lo_h(pa[0]), s[t0][1] - hi_h(pa[0]));
            pl[1] = packh2(s[t0][2] - lo_h(pa[1]), s[t0][3] - hi_h(pa[1]));
            pl[2] = packh2(s[t1][0] - lo_h(pa[2]), s[t1][1] - hi_h(pa[2]));
            pl[3] = packh2(s[t1][2] - lo_h(pa[3]), s[t1][3] - hi_h(pa[3]));
            const unsigned cof = kk * 16 * 2;
            unsigned vh_[8][2];
#pragma unroll
            for (int g = 0; g < 4; g++) {
                ldsm4(vh_[2 * g][0], vh_[2 * g][1], vh_[2 * g + 1][0], vh_[2 * g + 1][1],
                      vhA + g * (16 * 72 * 2) + cof);
            }
#pragma unroll
            for (int nt = 0; nt < 8; nt++) {
                mma_f16(o[nt], pa, vh_[nt][0], vh_[nt][1]);
                mma_f16(o[nt], pl, vh_[nt][0], vh_[nt][1]);
            }
        }
        __syncthreads();
    }

    // normalize + store split fp16 into [n][h*64+d]
    const float inv0 = 1.f / l0, inv1 = 1.f / l1;
    const int r = q0 + w * 16 + (lane >> 2);
#pragma unroll
    for (int nt = 0; nt < 8; nt++) {
        const int col = h * 64 + nt * 8 + (lane & 3) * 2;
        {
            float a = o[nt][0] * inv0, b = o[nt][1] * inv0;
            f16 ha = __float2half_rn(a), hb = __float2half_rn(b);
            f162 hh = __halves2half2(ha, hb);
            *(unsigned*)&g_ah[(size_t)r * DIM + col] = *(unsigned*)&hh;
            *(unsigned*)&g_al[(size_t)r * DIM + col] =
                packh2(a - __half2float(ha), b - __half2float(hb));
        }
        {
            float a = o[nt][2] * inv1, b = o[nt][3] * inv1;
            f16 ha = __float2half_rn(a), hb = __float2half_rn(b);
            f162 hh = __halves2half2(ha, hb);
            *(unsigned*)&g_ah[(size_t)(r + 8) * DIM + col] = *(unsigned*)&hh;
            *(unsigned*)&g_al[(size_t)(r + 8) * DIM + col] =
                packh2(a - __half2float(ha), b - __half2float(hb));
        }
    }
#undef FLASH_ISSUE
}

// ----------------------------------------------------------------------------
extern "C" void kernel_launch(void* const* d_in, const int* in_sizes, int n_in,
                              void* d_out, int out_size)
{
    (void)in_sizes; (void)n_in; (void)out_size;
    const float* x     = (const float*)d_in[0];
    const float* w_qkv = (const float*)d_in[1];
    const float* b_qkv = (const float*)d_in[2];
    const float* w_out = (const float*)d_in[3];
    const float* b_out = (const float*)d_in[4];
    float* out = (float*)d_out;

    f16 *xh, *xl, *wq, *wo, *ah, *al;
    cudaGetSymbolAddress((void**)&xh, g_xh); cudaGetSymbolAddress((void**)&xl, g_xl);
    cudaGetSymbolAddress((void**)&wq, g_wq); cudaGetSymbolAddress((void**)&wo, g_wo);
    cudaGetSymbolAddress((void**)&ah, g_ah); cudaGetSymbolAddress((void**)&al, g_al);

    const int gemm_smem = 2 * 3 * 128 * 40 * (int)sizeof(f16);   // 61440
    cudaFuncSetAttribute(gemm_f16x2<1, 3 * DIM, DIM>,
                         cudaFuncAttributeMaxDynamicSharedMemorySize, gemm_smem);
    cudaFuncSetAttribute(gemm_f16x2<0, DIM, DIM>,
                         cudaFuncAttributeMaxDynamicSharedMemorySize, gemm_smem);

    // 0) fp32 -> fp16 (x split; weights single-rounded)
    split_kernel<<<(SEQ * DIM + 255) / 256, 256>>>(x, xh, xl, SEQ * DIM);
    round_kernel<<<(3 * DIM * DIM + 255) / 256, 256>>>(w_qkv, wq, 3 * DIM * DIM);
    round_kernel<<<(DIM * DIM + 255) / 256, 256>>>(w_out, wo, DIM * DIM);

    // 1) QKV projection -> Q split / K single / V single-transposed
    {
        dim3 grid(3 * DIM / 128, SEQ / 128);   // (18, 32)
        gemm_f16x2<1, 3 * DIM, DIM><<<grid, 256, gemm_smem>>>(xh, xl, wq, b_qkv, nullptr);
    }

    // 2) flash attention
    {
        const int smem = 4 * 64 * 72 * (int)sizeof(f16);   // 36864
        cudaFuncSetAttribute(flash_mma,
                             cudaFuncAttributeMaxDynamicSharedMemorySize, smem);
        dim3 grid(SEQ / 128, NH);              // (32, 12)
        flash_mma<<<grid, 256, smem>>>();
    }

    // 3) output projection
    {
        dim3 grid(DIM / 128, SEQ / 128);       // (6, 32)
        gemm_f16x2<0, DIM, DIM><<<grid, 256, gemm_smem>>>(ah, al, wo, b_out, out);
    }
}